// round 4
// baseline (speedup 1.0000x reference)
#include <cuda_runtime.h>
#include <cuda_bf16.h>
#include <math.h>

#define BB 4096
#define LL 200
#define FF 8
#define DD 64
#define KK 15

__device__ __forceinline__ unsigned enc_f(float f) {
    unsigned u = __float_as_uint(f);
    return (u >> 31) ? ~u : (u ^ 0x80000000u);
}
__device__ __forceinline__ float dec_f(unsigned u) {
    unsigned bits = (u & 0x80000000u) ? (u ^ 0x80000000u) : ~u;
    return __uint_as_float(bits);
}

__global__ void __launch_bounds__(256) search_predict_kernel(
    const int* __restrict__ x,        // [B, L, F] int32
    const int* __restrict__ self_loc, // [B] int32
    const float* __restrict__ E,      // [NFEAT+1, D] float32
    float* __restrict__ out)          // [B*16*8] x_out-as-float, then [B*15] sim_topk
{
    const int b    = blockIdx.x;
    const int tid  = threadIdx.x;
    const int warp = tid >> 5;
    const int lane = tid & 31;
    const int grp  = lane >> 3;   // 4 groups of 8 lanes per warp; 1 row per group
    const int gl   = lane & 7;    // lane within group: covers 32B of a 256B row

    __shared__ __align__(16) unsigned long long keys[LL];  // exact (sim, -l) keys
    __shared__ __align__(16) unsigned simk[LL];            // 32-bit sim-only keys
    __shared__ unsigned long long selKey[KK];
    __shared__ int sortedL[KK + 1];
    __shared__ int bad;

    const int* xb = x + (size_t)b * (LL * FF);
    const int sl = __ldg(self_loc + b);

    // --- self embedding: every 8-lane group loads the full self row (broadcast) ---
    const int cself = __ldg(xb + sl * FF + 5);
    const float4* srow = reinterpret_cast<const float4*>(E + (size_t)cself * DD);
    const float4 s0 = __ldg(srow + gl * 2);
    const float4 s1 = __ldg(srow + gl * 2 + 1);
    float ssq_s = s0.x*s0.x + s0.y*s0.y + s0.z*s0.z + s0.w*s0.w
                + s1.x*s1.x + s1.y*s1.y + s1.z*s1.z + s1.w*s1.w;
    ssq_s += __shfl_xor_sync(0xffffffffu, ssq_s, 4);
    ssq_s += __shfl_xor_sync(0xffffffffu, ssq_s, 2);
    ssq_s += __shfl_xor_sync(0xffffffffu, ssq_s, 1);
    const float inv_nself = rsqrtf(ssq_s + 1e-8f);

    if (tid == 0) bad = 0;

    // --- cosine sims: 32 rows/block-iter (4 rows/warp), branch-free, fully unrolled ---
    #pragma unroll
    for (int it = 0; it < 7; ++it) {
        const int l    = it * 32 + warp * 4 + grp;       // unique l in [0, 224)
        const int lidx = (l < LL) ? l : (LL - 1);        // clamp for safe loads
        const int c = __ldg(xb + lidx * FF + 5);
        const float4* row = reinterpret_cast<const float4*>(E + (size_t)c * DD);
        const float4 v0 = __ldg(row + gl * 2);
        const float4 v1 = __ldg(row + gl * 2 + 1);
        float dot = v0.x*s0.x + v0.y*s0.y + v0.z*s0.z + v0.w*s0.w
                  + v1.x*s1.x + v1.y*s1.y + v1.z*s1.z + v1.w*s1.w;
        float ssq = v0.x*v0.x + v0.y*v0.y + v0.z*v0.z + v0.w*v0.w
                  + v1.x*v1.x + v1.y*v1.y + v1.z*v1.z + v1.w*v1.w;
        dot += __shfl_xor_sync(0xffffffffu, dot, 4);
        ssq += __shfl_xor_sync(0xffffffffu, ssq, 4);
        dot += __shfl_xor_sync(0xffffffffu, dot, 2);
        ssq += __shfl_xor_sync(0xffffffffu, ssq, 2);
        dot += __shfl_xor_sync(0xffffffffu, dot, 1);
        ssq += __shfl_xor_sync(0xffffffffu, ssq, 1);
        const float val = dot * rsqrtf(ssq + 1e-8f) * inv_nself;
        const float sim = (l < sl) ? val : -2.0f;
        if (gl == 0 && l < LL) {
            const unsigned e = enc_f(sim);
            simk[l] = e;
            keys[l] = ((unsigned long long)e << 32) | (unsigned)(LL - 1 - l);
        }
    }
    __syncthreads();

    // --- fast rank: 32-bit strict-greater count (ties collapse to equal rank) ---
    int rank = LL;
    unsigned long long myKey = 0ull;
    {
        const unsigned myEnc = (tid < LL) ? simk[tid] : 0xFFFFFFFFu;
        if (tid < LL) myKey = keys[tid];
        int r = 0;
        const uint4* p = reinterpret_cast<const uint4*>(simk);
        #pragma unroll 10
        for (int j = 0; j < LL / 4; ++j) {           // broadcast LDS.128
            const uint4 k = p[j];
            r += (k.x > myEnc);
            r += (k.y > myEnc);
            r += (k.z > myEnc);
            r += (k.w > myEnc);
        }
        if (tid < LL) rank = r;
        if (rank < KK) selKey[rank] = myKey;
    }
    __syncthreads();

    // --- tie detection: a top-15 tie makes two threads share a slot; loser flags ---
    if (rank < KK && selKey[rank] != myKey) bad = 1;
    __syncthreads();

    if (bad) {   // exact 64-bit tie-aware recount (rare: ~3% of blocks)
        int r2 = 0;
        const ulonglong2* k2 = reinterpret_cast<const ulonglong2*>(keys);
        #pragma unroll 10
        for (int j = 0; j < LL / 2; ++j) {
            const ulonglong2 kk = k2[j];
            r2 += (kk.x > myKey);
            r2 += (kk.y > myKey);
        }
        if (tid < LL && r2 < KK) selKey[r2] = myKey;
        __syncthreads();
    }

    // --- sort the 15 selected by ascending index; emit sim_topk ---
    if (tid < KK) {
        const unsigned long long mk = selKey[tid];
        const unsigned myLow = (unsigned)mk;        // 199 - l (larger = smaller l)
        int pos = 0;
        #pragma unroll
        for (int j = 0; j < KK; ++j) pos += ((unsigned)selKey[j] > myLow);
        const int l = LL - 1 - (int)myLow;
        sortedL[pos] = l;
        out[(size_t)BB * ((KK + 1) * FF) + (size_t)b * KK + pos] = dec_f((unsigned)(mk >> 32));
    }
    if (tid == KK) sortedL[KK] = sl;
    __syncthreads();

    // --- x_out: [16 rows x 8 feats] as float ---
    if (tid < (KK + 1) * FF) {
        const int r = tid >> 3;
        const int f = tid & 7;
        const int l = sortedL[r];
        out[(size_t)b * ((KK + 1) * FF) + tid] = (float)__ldg(xb + l * FF + f);
    }
}

extern "C" void kernel_launch(void* const* d_in, const int* in_sizes, int n_in,
                              void* d_out, int out_size) {
    const int*   x  = (const int*)d_in[0];   // x: [4096, 200, 8] int32
    const int*   sl = (const int*)d_in[1];   // self_loc: [4096] int32
    const float* E  = (const float*)d_in[2]; // E: [100001, 64] float32
    float* out = (float*)d_out;

    search_predict_kernel<<<BB, 256>>>(x, sl, E, out);
}

// round 5
// speedup vs baseline: 1.5793x; 1.5793x over previous
#include <cuda_runtime.h>
#include <cuda_bf16.h>
#include <math.h>

#define BB 4096
#define LL 200
#define FF 8
#define DD 64
#define KK 15
#define SMEM_BYTES (LL * DD * 4)   // 51200 B staged embedding rows (aliased by keys)

__device__ __forceinline__ unsigned enc_f(float f) {
    unsigned u = __float_as_uint(f);
    return (u >> 31) ? ~u : (u ^ 0x80000000u);
}
__device__ __forceinline__ float dec_f(unsigned u) {
    unsigned bits = (u & 0x80000000u) ? (u ^ 0x80000000u) : ~u;
    return __uint_as_float(bits);
}

__global__ void __launch_bounds__(256) search_predict_kernel(
    const int* __restrict__ x,        // [B, L, F] int32
    const int* __restrict__ self_loc, // [B] int32
    const float* __restrict__ E,      // [NFEAT+1, D] float32
    float* __restrict__ out)          // [B*16*8] x_out-as-float, then [B*15] sim_topk
{
    extern __shared__ __align__(16) char buf[];
    float* erows = reinterpret_cast<float*>(buf);                       // [200][64] swizzled
    unsigned long long* keys = reinterpret_cast<unsigned long long*>(buf);        // alias
    unsigned* simk = reinterpret_cast<unsigned*>(buf + 224 * 8);                  // alias

    __shared__ int catS[LL];
    __shared__ unsigned long long selKey[KK];
    __shared__ int sortedL[KK + 1];
    __shared__ float invns;
    __shared__ int bad;

    const int b    = blockIdx.x;
    const int tid  = threadIdx.x;
    const int warp = tid >> 5;
    const int lane = tid & 31;

    const int* xb = x + (size_t)b * (LL * FF);
    const int sl = __ldg(self_loc + b);

    if (tid == 0) bad = 0;
    if (tid < LL) catS[tid] = __ldg(xb + tid * FF + 5);
    __syncthreads();

    // ---- Phase A: stage all 200 embedding rows into smem (swizzled, conflict-free)
    {
        const int half = lane >> 4;     // two rows per warp per iteration
        const int hi   = lane & 15;     // float4 index within row
        #pragma unroll
        for (int it = 0; it < 13; ++it) {
            const int l = it * 16 + (warp << 1) + half;
            if (l < LL) {
                const int c = catS[l];
                const float4 v = __ldg(reinterpret_cast<const float4*>(E + (size_t)c * DD) + hi);
                const int isw = hi ^ (l & 7);                 // XOR swizzle
                *reinterpret_cast<float4*>(erows + l * DD + (isw << 2)) = v;
            }
        }
    }
    __syncthreads();

    // ---- Phase B: one thread per row, dot + ssq from smem (no shuffles)
    float dot, ssq;
    {
        const int t   = (tid < LL) ? tid : 0;     // clamp; extra threads discarded later
        const float* vr = erows + t * DD;
        const float* sr = erows + sl * DD;
        const int tsw = t & 7, ssw = sl & 7;
        float d0 = 0.f, d1 = 0.f, q0 = 0.f, q1 = 0.f;
        #pragma unroll
        for (int i = 0; i < 16; i += 2) {
            const float4 v = *reinterpret_cast<const float4*>(vr + ((i ^ tsw) << 2));
            const float4 s = *reinterpret_cast<const float4*>(sr + ((i ^ ssw) << 2));
            d0 += v.x * s.x + v.y * s.y + v.z * s.z + v.w * s.w;
            q0 += v.x * v.x + v.y * v.y + v.z * v.z + v.w * v.w;
            const float4 v2 = *reinterpret_cast<const float4*>(vr + (((i + 1) ^ tsw) << 2));
            const float4 s2 = *reinterpret_cast<const float4*>(sr + (((i + 1) ^ ssw) << 2));
            d1 += v2.x * s2.x + v2.y * s2.y + v2.z * s2.z + v2.w * s2.w;
            q1 += v2.x * v2.x + v2.y * v2.y + v2.z * v2.z + v2.w * v2.w;
        }
        dot = d0 + d1;
        ssq = q0 + q1;
    }
    if (tid == sl) invns = rsqrtf(ssq + 1e-8f);   // self row's norm (row sl == self)
    __syncthreads();                               // also separates erows reads from key writes

    const float sim = (tid < sl) ? dot * rsqrtf(ssq + 1e-8f) * invns : -2.0f;
    const unsigned e = enc_f(sim);
    const unsigned long long myKey =
        ((unsigned long long)e << 32) | (unsigned)(LL - 1 - tid);
    if (tid < 224) { keys[tid] = myKey; simk[tid] = e; }   // 200..223 = pad (enc(-2), inert)
    __syncthreads();

    // ---- rank-select among the first sl keys only (invalid rows can't win: sl >= K)
    int rank = LL;
    if (tid < sl) {
        int r = 0;
        const uint4* p = reinterpret_cast<const uint4*>(simk);
        const int nj = (sl + 3) >> 2;
        for (int j = 0; j < nj; ++j) {            // broadcast LDS.128
            const uint4 k = p[j];
            r += (k.x > e);
            r += (k.y > e);
            r += (k.z > e);
            r += (k.w > e);
        }
        rank = r;
        if (r < KK) selKey[r] = myKey;
    }
    __syncthreads();

    // tie inside top-K -> two threads shared a slot -> loser flags; rare
    if (rank < KK && selKey[rank] != myKey) bad = 1;
    __syncthreads();

    if (bad) {   // exact 64-bit tie-aware recount (keys strictly unique)
        if (tid < sl) {
            int r2 = 0;
            const ulonglong2* k2 = reinterpret_cast<const ulonglong2*>(keys);
            const int nj2 = (sl + 1) >> 1;
            for (int j = 0; j < nj2; ++j) {
                const ulonglong2 kk = k2[j];
                r2 += (kk.x > myKey);
                r2 += (kk.y > myKey);
            }
            if (r2 < KK) selKey[r2] = myKey;
        }
        __syncthreads();
    }

    // ---- sort the 15 selected by ascending index; emit sim_topk
    if (tid < KK) {
        const unsigned long long mk = selKey[tid];
        const unsigned myLow = (unsigned)mk;        // 199 - l (larger = smaller l)
        int pos = 0;
        #pragma unroll
        for (int j = 0; j < KK; ++j) pos += ((unsigned)selKey[j] > myLow);
        const int l = LL - 1 - (int)myLow;
        sortedL[pos] = l;
        out[(size_t)BB * ((KK + 1) * FF) + (size_t)b * KK + pos] = dec_f((unsigned)(mk >> 32));
    }
    if (tid == KK) sortedL[KK] = sl;
    __syncthreads();

    // ---- x_out: [16 rows x 8 feats] as float
    if (tid < (KK + 1) * FF) {
        const int r = tid >> 3;
        const int f = tid & 7;
        const int l = sortedL[r];
        out[(size_t)b * ((KK + 1) * FF) + tid] = (float)__ldg(xb + l * FF + f);
    }
}

extern "C" void kernel_launch(void* const* d_in, const int* in_sizes, int n_in,
                              void* d_out, int out_size) {
    const int*   x  = (const int*)d_in[0];   // x: [4096, 200, 8] int32
    const int*   sl = (const int*)d_in[1];   // self_loc: [4096] int32
    const float* E  = (const float*)d_in[2]; // E: [100001, 64] float32
    float* out = (float*)d_out;

    cudaFuncSetAttribute(search_predict_kernel,
                         cudaFuncAttributeMaxDynamicSharedMemorySize, SMEM_BYTES);
    search_predict_kernel<<<BB, 256, SMEM_BYTES>>>(x, sl, E, out);
}

// round 6
// speedup vs baseline: 2.0374x; 1.2901x over previous
#include <cuda_runtime.h>
#include <cuda_bf16.h>
#include <math.h>

#define BB 4096
#define LL 200
#define FF 8
#define DD 64
#define KK 15
// dynamic smem: per-row partial (dot, ssq) pairs: [200][16] float2, swizzled
#define SMEM_BYTES (LL * 16 * 8)   // 25600 B

__device__ __forceinline__ unsigned enc_f(float f) {
    unsigned u = __float_as_uint(f);
    return (u >> 31) ? ~u : (u ^ 0x80000000u);
}
__device__ __forceinline__ float dec_f(unsigned u) {
    unsigned bits = (u & 0x80000000u) ? (u ^ 0x80000000u) : ~u;
    return __uint_as_float(bits);
}

__global__ void __launch_bounds__(256) search_predict_kernel(
    const int* __restrict__ x,        // [B, L, F] int32
    const int* __restrict__ self_loc, // [B] int32
    const float* __restrict__ E,      // [NFEAT+1, D] float32
    float* __restrict__ out)          // [B*16*8] x_out-as-float, then [B*15] sim_topk
{
    extern __shared__ __align__(16) float partials[];   // [200][16] float2, swizzled

    __shared__ __align__(16) float4 selfv[16];          // self embedding row
    __shared__ int catS[LL];
    __shared__ __align__(16) unsigned long long keys[224];
    __shared__ __align__(16) unsigned simk[224];
    __shared__ unsigned long long selKey[KK];
    __shared__ int sortedL[KK + 1];
    __shared__ float invns;
    __shared__ int bad;

    const int b   = blockIdx.x;
    const int tid = threadIdx.x;

    const int* xb = x + (size_t)b * (LL * FF);
    const int sl = __ldg(self_loc + b);

    if (tid == 0) bad = 0;
    // catS by threads 0..199; self row by threads 224..239 (disjoint warps)
    if (tid < LL) catS[tid] = __ldg(xb + tid * FF + 5);
    if (tid >= 224 && tid < 240) {
        const int cs = __ldg(xb + sl * FF + 5);
        selfv[tid - 224] = __ldg(reinterpret_cast<const float4*>(E + (size_t)cs * DD) + (tid - 224));
    }
    __syncthreads();

    // ---- Phase A: fused gather + partial dot/ssq. 16 threads per row. ----
    {
        const int rgrp = tid >> 4;        // row group 0..15
        const int l16  = tid & 15;        // float4 slice within row
        const float4 s = selfv[l16];      // register-resident self slice
        #pragma unroll
        for (int it = 0; it < 13; ++it) {
            const int l = it * 16 + rgrp;
            if (l < LL) {
                const int c = catS[l];
                const float4 v = __ldg(reinterpret_cast<const float4*>(E + (size_t)c * DD) + l16);
                const float dp = v.x * s.x + v.y * s.y + v.z * s.z + v.w * s.w;
                const float qp = v.x * v.x + v.y * v.y + v.z * v.z + v.w * v.w;
                // partial j=l16 of row l lives in float4-chunk (j>>1)^(l&7), half j&1
                const int byteoff = l * 128 + ((((l16 >> 1) ^ (l & 7)) << 4) | ((l16 & 1) << 3));
                *reinterpret_cast<float2*>(reinterpret_cast<char*>(partials) + byteoff)
                    = make_float2(dp, qp);
            }
        }
    }
    __syncthreads();

    // ---- Phase B: thread-per-row reduction of 16 partials (8 swizzled LDS.128) ----
    float dot = 0.f, ssq = 0.f;
    {
        const int t = (tid < LL) ? tid : 0;
        const float4* pr = reinterpret_cast<const float4*>(partials) + t * 8;
        const int tsw = t & 7;
        #pragma unroll
        for (int k = 0; k < 8; ++k) {
            const float4 c = pr[k ^ tsw];   // (dot_{2k}, ssq_{2k}, dot_{2k+1}, ssq_{2k+1})
            dot += c.x + c.z;
            ssq += c.y + c.w;
        }
    }
    if (tid == sl) invns = rsqrtf(ssq + 1e-8f);   // row sl's ssq is the self norm^2
    __syncthreads();

    const float sim = (tid < sl) ? dot * rsqrtf(ssq + 1e-8f) * invns : -2.0f;
    const unsigned e = enc_f(sim);
    const unsigned long long myKey =
        ((unsigned long long)e << 32) | (unsigned)(LL - 1 - tid);
    if (tid < 224) { keys[tid] = myKey; simk[tid] = e; }   // 200..223 pad, never read
    __syncthreads();

    // ---- rank-select among the first sl keys only (invalid rows can't win) ----
    int rank = LL;
    if (tid < sl) {
        int r = 0;
        const uint4* p = reinterpret_cast<const uint4*>(simk);
        const int nj = (sl + 3) >> 2;
        for (int j = 0; j < nj; ++j) {            // broadcast LDS.128
            const uint4 k = p[j];
            r += (k.x > e);
            r += (k.y > e);
            r += (k.z > e);
            r += (k.w > e);
        }
        rank = r;
        if (r < KK) selKey[r] = myKey;
    }
    __syncthreads();

    // tie inside top-K -> two threads shared a slot -> loser flags; rare
    if (rank < KK && selKey[rank] != myKey) bad = 1;
    __syncthreads();

    if (bad) {   // exact 64-bit tie-aware recount (keys strictly unique)
        if (tid < sl) {
            int r2 = 0;
            const ulonglong2* k2 = reinterpret_cast<const ulonglong2*>(keys);
            const int nj2 = (sl + 1) >> 1;
            for (int j = 0; j < nj2; ++j) {
                const ulonglong2 kk = k2[j];
                r2 += (kk.x > myKey);
                r2 += (kk.y > myKey);
            }
            if (r2 < KK) selKey[r2] = myKey;
        }
        __syncthreads();
    }

    // ---- sort the 15 selected by ascending index; emit sim_topk ----
    if (tid < KK) {
        const unsigned long long mk = selKey[tid];
        const unsigned myLow = (unsigned)mk;        // 199 - l (larger = smaller l)
        int pos = 0;
        #pragma unroll
        for (int j = 0; j < KK; ++j) pos += ((unsigned)selKey[j] > myLow);
        const int l = LL - 1 - (int)myLow;
        sortedL[pos] = l;
        out[(size_t)BB * ((KK + 1) * FF) + (size_t)b * KK + pos] = dec_f((unsigned)(mk >> 32));
    }
    if (tid == KK) sortedL[KK] = sl;
    __syncthreads();

    // ---- x_out: [16 rows x 8 feats] as float ----
    if (tid < (KK + 1) * FF) {
        const int r = tid >> 3;
        const int f = tid & 7;
        const int l = sortedL[r];
        out[(size_t)b * ((KK + 1) * FF) + tid] = (float)__ldg(xb + l * FF + f);
    }
}

extern "C" void kernel_launch(void* const* d_in, const int* in_sizes, int n_in,
                              void* d_out, int out_size) {
    const int*   x  = (const int*)d_in[0];   // x: [4096, 200, 8] int32
    const int*   sl = (const int*)d_in[1];   // self_loc: [4096] int32
    const float* E  = (const float*)d_in[2]; // E: [100001, 64] float32
    float* out = (float*)d_out;

    search_predict_kernel<<<BB, 256, SMEM_BYTES>>>(x, sl, E, out);
}

// round 7
// speedup vs baseline: 2.6670x; 1.3090x over previous
#include <cuda_runtime.h>
#include <cuda_bf16.h>
#include <math.h>

#define BB 4096
#define LL 200
#define FF 8
#define DD 64
#define KK 15
// dynamic smem: per-row partials [200][8] float2 (each = dot/ssq over 8 floats)
#define SMEM_BYTES (LL * 8 * 8)   // 12800 B

__device__ __forceinline__ unsigned enc_f(float f) {
    unsigned u = __float_as_uint(f);
    return (u >> 31) ? ~u : (u ^ 0x80000000u);
}
__device__ __forceinline__ float dec_f(unsigned u) {
    unsigned bits = (u & 0x80000000u) ? (u ^ 0x80000000u) : ~u;
    return __uint_as_float(bits);
}

__global__ void __launch_bounds__(256) search_predict_kernel(
    const int* __restrict__ x,        // [B, L, F] int32
    const int* __restrict__ self_loc, // [B] int32
    const float* __restrict__ E,      // [NFEAT+1, D] float32
    float* __restrict__ out)          // [B*16*8] x_out-as-float, then [B*15] sim_topk
{
    extern __shared__ __align__(16) float partials[];   // [200][8] float2, rot-swizzled

    __shared__ __align__(16) float4 selfv[16];          // self embedding row
    __shared__ int catS[LL];
    __shared__ __align__(16) unsigned long long keys[224];
    __shared__ __align__(16) unsigned simk[224];
    __shared__ unsigned long long selKey[KK];
    __shared__ int sortedL[KK + 1];
    __shared__ float invns;
    __shared__ int bad;

    const int b   = blockIdx.x;
    const int tid = threadIdx.x;

    const int* xb = x + (size_t)b * (LL * FF);
    const int sl = __ldg(self_loc + b);

    if (tid == 0) bad = 0;
    // catS by threads 0..199; self row by threads 224..239 (disjoint warp)
    if (tid < LL) catS[tid] = __ldg(xb + tid * FF + 5);
    if (tid >= 224 && tid < 240) {
        const int cs = __ldg(xb + sl * FF + 5);
        selfv[tid - 224] = __ldg(reinterpret_cast<const float4*>(E + (size_t)cs * DD) + (tid - 224));
    }
    __syncthreads();

    // ---- Phase A: fused gather + partials. 8 threads/row, 2x LDG.128 each. ----
    {
        const int rg = tid >> 3;          // row within 32-row tile
        const int j8 = tid & 7;           // owns float4 slices j8 and j8+8
        const float4 sa = selfv[j8];
        const float4 sb = selfv[j8 + 8];
        #pragma unroll
        for (int it = 0; it < 7; ++it) {
            const int l = it * 32 + rg;
            if (l < LL) {
                const int c = catS[l];
                const float4* rp = reinterpret_cast<const float4*>(E + (size_t)c * DD);
                const float4 va = __ldg(rp + j8);
                const float4 vb = __ldg(rp + j8 + 8);
                const float dp = va.x*sa.x + va.y*sa.y + va.z*sa.z + va.w*sa.w
                               + vb.x*sb.x + vb.y*sb.y + vb.z*sb.z + vb.w*sb.w;
                const float qp = va.x*va.x + va.y*va.y + va.z*va.z + va.w*va.w
                               + vb.x*vb.x + vb.y*vb.y + vb.z*vb.z + vb.w*vb.w;
                // rotation swizzle: partial j8 of row l -> 16B chunk ((j8>>1)+(l>>1))&3
                const int byteoff = l * 64 + ((((j8 >> 1) + (l >> 1)) & 3) << 4)
                                  + ((j8 & 1) << 3);
                *reinterpret_cast<float2*>(reinterpret_cast<char*>(partials) + byteoff)
                    = make_float2(dp, qp);
            }
        }
    }
    __syncthreads();

    // ---- Phase B: thread-per-row reduction of 8 partials (4 rotated LDS.128) ----
    float dot = 0.f, ssq = 0.f;
    {
        const int t = (tid < LL) ? tid : 0;
        const char* base = reinterpret_cast<const char*>(partials) + t * 64;
        const int rot = (t >> 1) & 3;
        #pragma unroll
        for (int k = 0; k < 4; ++k) {
            const float4 c = *reinterpret_cast<const float4*>(base + (((k + rot) & 3) << 4));
            dot += c.x + c.z;   // (dot_j, ssq_j, dot_{j+1}, ssq_{j+1})
            ssq += c.y + c.w;
        }
    }
    if (tid == sl) invns = rsqrtf(ssq + 1e-8f);   // row sl's ssq is the self norm^2
    __syncthreads();

    const float sim = (tid < sl) ? dot * rsqrtf(ssq + 1e-8f) * invns : -2.0f;
    const unsigned e = enc_f(sim);
    const unsigned long long myKey =
        ((unsigned long long)e << 32) | (unsigned)(LL - 1 - tid);
    if (tid < 224) { keys[tid] = myKey; simk[tid] = e; }   // 200..223 pad, never read
    __syncthreads();

    // ---- rank-select among the first sl keys only (invalid rows can't win) ----
    int rank = LL;
    if (tid < sl) {
        int r = 0;
        const uint4* p = reinterpret_cast<const uint4*>(simk);
        const int nj = (sl + 3) >> 2;
        for (int j = 0; j < nj; ++j) {            // broadcast LDS.128
            const uint4 k = p[j];
            r += (k.x > e);
            r += (k.y > e);
            r += (k.z > e);
            r += (k.w > e);
        }
        rank = r;
        if (r < KK) selKey[r] = myKey;
    }
    __syncthreads();

    // tie inside top-K -> two threads shared a slot -> loser flags; rare
    if (rank < KK && selKey[rank] != myKey) bad = 1;
    __syncthreads();

    if (bad) {   // exact 64-bit tie-aware recount (keys strictly unique)
        if (tid < sl) {
            int r2 = 0;
            const ulonglong2* k2 = reinterpret_cast<const ulonglong2*>(keys);
            const int nj2 = (sl + 1) >> 1;
            for (int j = 0; j < nj2; ++j) {
                const ulonglong2 kk = k2[j];
                r2 += (kk.x > myKey);
                r2 += (kk.y > myKey);
            }
            if (r2 < KK) selKey[r2] = myKey;
        }
        __syncthreads();
    }

    // ---- sort the 15 selected by ascending index; emit sim_topk ----
    if (tid < KK) {
        const unsigned long long mk = selKey[tid];
        const unsigned myLow = (unsigned)mk;        // 199 - l (larger = smaller l)
        int pos = 0;
        #pragma unroll
        for (int j = 0; j < KK; ++j) pos += ((unsigned)selKey[j] > myLow);
        const int l = LL - 1 - (int)myLow;
        sortedL[pos] = l;
        out[(size_t)BB * ((KK + 1) * FF) + (size_t)b * KK + pos] = dec_f((unsigned)(mk >> 32));
    }
    if (tid == KK) sortedL[KK] = sl;
    __syncthreads();

    // ---- x_out: [16 rows x 8 feats] as float ----
    if (tid < (KK + 1) * FF) {
        const int r = tid >> 3;
        const int f = tid & 7;
        const int l = sortedL[r];
        out[(size_t)b * ((KK + 1) * FF) + tid] = (float)__ldg(xb + l * FF + f);
    }
}

extern "C" void kernel_launch(void* const* d_in, const int* in_sizes, int n_in,
                              void* d_out, int out_size) {
    const int*   x  = (const int*)d_in[0];   // x: [4096, 200, 8] int32
    const int*   sl = (const int*)d_in[1];   // self_loc: [4096] int32
    const float* E  = (const float*)d_in[2]; // E: [100001, 64] float32
    float* out = (float*)d_out;

    search_predict_kernel<<<BB, 256, SMEM_BYTES>>>(x, sl, E, out);
}

// round 8
// speedup vs baseline: 3.1263x; 1.1722x over previous
#include <cuda_runtime.h>
#include <cuda_bf16.h>
#include <math.h>

#define BB 4096
#define LL 200
#define FF 8
#define DD 64
#define KK 15
// dynamic smem: per-row partials [200][8] float2 (each = dot/ssq over 8 floats)
#define SMEM_BYTES (LL * 8 * 8)   // 12800 B

__device__ __forceinline__ unsigned enc_f(float f) {
    unsigned u = __float_as_uint(f);
    return (u >> 31) ? ~u : (u ^ 0x80000000u);
}
__device__ __forceinline__ float dec_f(unsigned u) {
    unsigned bits = (u & 0x80000000u) ? (u ^ 0x80000000u) : ~u;
    return __uint_as_float(bits);
}

__global__ void __launch_bounds__(256) search_predict_kernel(
    const int* __restrict__ x,        // [B, L, F] int32
    const int* __restrict__ self_loc, // [B] int32
    const float* __restrict__ E,      // [NFEAT+1, D] float32
    float* __restrict__ out)          // [B*16*8] x_out-as-float, then [B*15] sim_topk
{
    extern __shared__ __align__(16) float partials[];   // [200][8] float2, rot-swizzled

    __shared__ __align__(16) float4 selfv[16];          // self embedding row
    __shared__ int catS[LL];
    __shared__ __align__(16) unsigned long long keys[224];
    __shared__ __align__(16) unsigned simk[224];
    __shared__ unsigned long long selKey[KK];
    __shared__ int sortedL[KK + 1];
    __shared__ float invns;
    __shared__ int bad;

    const int b   = blockIdx.x;
    const int tid = threadIdx.x;
    const int warp = tid >> 5;

    const int* xb = x + (size_t)b * (LL * FF);
    const int sl = __ldg(self_loc + b);

    if (tid == 0) bad = 0;
    // catS by threads 0..199; warp 7 loads self row AND precomputes its inv-norm
    if (tid < LL) catS[tid] = __ldg(xb + tid * FF + 5);
    if (warp == 7) {
        const int hl = tid & 15;
        if ((tid & 31) < 16) {
            const int cs = __ldg(xb + sl * FF + 5);
            selfv[hl] = __ldg(reinterpret_cast<const float4*>(E + (size_t)cs * DD) + hl);
        }
        __syncwarp();
        const float4 s = selfv[hl];                       // lanes 16-31 mirror 0-15
        float q = s.x * s.x + s.y * s.y + s.z * s.z + s.w * s.w;
        q += __shfl_xor_sync(0xffffffffu, q, 8);
        q += __shfl_xor_sync(0xffffffffu, q, 4);
        q += __shfl_xor_sync(0xffffffffu, q, 2);
        q += __shfl_xor_sync(0xffffffffu, q, 1);
        if (tid == 224) invns = rsqrtf(q + 1e-8f);
    }
    __syncthreads();

    // ---- Phase A: fused gather + partials, ONLY rows l <= sl (others can't win) ----
    {
        const int rg = tid >> 3;          // row within 32-row tile
        const int j8 = tid & 7;           // owns float4 slices j8 and j8+8
        const float4 sa = selfv[j8];
        const float4 sb = selfv[j8 + 8];
        #pragma unroll
        for (int it = 0; it < 7; ++it) {
            const int l = it * 32 + rg;
            if (l <= sl) {                // warp-uniform except one boundary warp
                const int c = catS[l];
                const float4* rp = reinterpret_cast<const float4*>(E + (size_t)c * DD);
                const float4 va = __ldg(rp + j8);
                const float4 vb = __ldg(rp + j8 + 8);
                const float dp = va.x*sa.x + va.y*sa.y + va.z*sa.z + va.w*sa.w
                               + vb.x*sb.x + vb.y*sb.y + vb.z*sb.z + vb.w*sb.w;
                const float qp = va.x*va.x + va.y*va.y + va.z*va.z + va.w*va.w
                               + vb.x*vb.x + vb.y*vb.y + vb.z*vb.z + vb.w*vb.w;
                // rotation swizzle: partial j8 of row l -> 16B chunk ((j8>>1)+(l>>1))&3
                const int byteoff = l * 64 + ((((j8 >> 1) + (l >> 1)) & 3) << 4)
                                  + ((j8 & 1) << 3);
                *reinterpret_cast<float2*>(reinterpret_cast<char*>(partials) + byteoff)
                    = make_float2(dp, qp);
            }
        }
    }
    __syncthreads();

    // ---- Phase B: thread-per-row reduction, only rows <= sl (rest discarded) ----
    float dot = 0.f, ssq = 0.f;
    if (tid <= sl) {
        const char* base = reinterpret_cast<const char*>(partials) + tid * 64;
        const int rot = (tid >> 1) & 3;
        #pragma unroll
        for (int k = 0; k < 4; ++k) {     // logical chunk order fixed (bit-exact dups)
            const float4 c = *reinterpret_cast<const float4*>(base + (((k + rot) & 3) << 4));
            dot += c.x + c.z;
            ssq += c.y + c.w;
        }
    }
    const float sim = (tid < sl) ? dot * rsqrtf(ssq + 1e-8f) * invns : -2.0f;
    const unsigned e = enc_f(sim);
    const unsigned long long myKey =
        ((unsigned long long)e << 32) | (unsigned)(LL - 1 - tid);
    if (tid < 224) { keys[tid] = myKey; simk[tid] = e; }   // 200..223 pad, inert
    __syncthreads();

    // ---- rank-select among the first sl keys only ----
    int rank = LL;
    if (tid < sl) {
        int r = 0;
        const uint4* p = reinterpret_cast<const uint4*>(simk);
        const int nj = (sl + 3) >> 2;
        for (int j = 0; j < nj; ++j) {            // broadcast LDS.128
            const uint4 k = p[j];
            r += (k.x > e);
            r += (k.y > e);
            r += (k.z > e);
            r += (k.w > e);
        }
        rank = r;
        if (r < KK) selKey[r] = myKey;
    }
    __syncthreads();

    // tie inside top-K -> two threads shared a slot -> loser flags; rare
    if (rank < KK && selKey[rank] != myKey) bad = 1;
    __syncthreads();

    if (bad) {   // exact 64-bit tie-aware recount (keys strictly unique)
        if (tid < sl) {
            int r2 = 0;
            const ulonglong2* k2 = reinterpret_cast<const ulonglong2*>(keys);
            const int nj2 = (sl + 1) >> 1;
            for (int j = 0; j < nj2; ++j) {
                const ulonglong2 kk = k2[j];
                r2 += (kk.x > myKey);
                r2 += (kk.y > myKey);
            }
            if (r2 < KK) selKey[r2] = myKey;
        }
        __syncthreads();
    }

    // ---- sort the 15 selected by ascending index; emit sim_topk ----
    if (tid < KK) {
        const unsigned long long mk = selKey[tid];
        const unsigned myLow = (unsigned)mk;        // 199 - l (larger = smaller l)
        int pos = 0;
        #pragma unroll
        for (int j = 0; j < KK; ++j) pos += ((unsigned)selKey[j] > myLow);
        const int l = LL - 1 - (int)myLow;
        sortedL[pos] = l;
        out[(size_t)BB * ((KK + 1) * FF) + (size_t)b * KK + pos] = dec_f((unsigned)(mk >> 32));
    }
    if (tid == KK) sortedL[KK] = sl;
    __syncthreads();

    // ---- x_out: [16 rows x 8 feats] as float ----
    if (tid < (KK + 1) * FF) {
        const int r = tid >> 3;
        const int f = tid & 7;
        const int l = sortedL[r];
        out[(size_t)b * ((KK + 1) * FF) + tid] = (float)__ldg(xb + l * FF + f);
    }
}

extern "C" void kernel_launch(void* const* d_in, const int* in_sizes, int n_in,
                              void* d_out, int out_size) {
    const int*   x  = (const int*)d_in[0];   // x: [4096, 200, 8] int32
    const int*   sl = (const int*)d_in[1];   // self_loc: [4096] int32
    const float* E  = (const float*)d_in[2]; // E: [100001, 64] float32
    float* out = (float*)d_out;

    search_predict_kernel<<<BB, 256, SMEM_BYTES>>>(x, sl, E, out);
}